// round 2
// baseline (speedup 1.0000x reference)
#include <cuda_runtime.h>
#include <math.h>

#define B    8
#define NPTS 2048
#define BN   (B * NPTS)
#define CMAT ((size_t)B * NPTS * NPTS)

// ---------------- scratch (allocation-free: __device__ globals) ----------------
// 0 = Cxx, 1 = Cyy, 2 = Cxy, 3 = Cyx (= Cxy^T, recomputed for contiguous reads)
__device__ float d_C[4][B * NPTS * NPTS];     // 4 * 134 MB = 537 MB
__device__ float d_pot[2][4][BN];             // ping-pong potentials: a_x, b_y, a_y, b_x
__device__ float d_fin[4][BN];                // final extrapolated potentials
__device__ float d_la[BN];
__device__ float d_lb[BN];

// ---------------- kernels ----------------

__global__ void logw_kernel(const float* __restrict__ a, const float* __restrict__ bt,
                            float* __restrict__ la, float* __restrict__ lb) {
    int i = blockIdx.x * blockDim.x + threadIdx.x;
    if (i < BN) {
        float av = a[i];
        la[i] = (av > 0.f) ? logf(fmaxf(av, 1e-30f)) : -1e5f;
        float bv = bt[i];
        lb[i] = (bv > 0.f) ? logf(fmaxf(bv, 1e-30f)) : -1e5f;
    }
}

// C[b,n,m] = acos(clip(P[b,n]·Q[b,m], -1+1e-6, 1-1e-6)) * 0.5
__global__ void cost_kernel(const float* __restrict__ P, const float* __restrict__ Q,
                            float* __restrict__ C) {
    int m = blockIdx.x * blockDim.x + threadIdx.x;
    int n = blockIdx.y;
    int b = blockIdx.z;
    const float* p = P + ((size_t)b * NPTS + n) * 3;
    const float* q = Q + ((size_t)b * NPTS + m) * 3;
    float t = p[0] * q[0] + p[1] * q[1] + p[2] * q[2];
    t = fminf(fmaxf(t, -1.0f + 1e-6f), 1.0f - 1e-6f);
    C[((size_t)b * NPTS + n) * NPTS + m] = acosf(t) * 0.5f;
}

// out[row] = blend-combine( -eps * logsumexp_m( lw[b,m] + potg[b,m]/eps - C[row,m]/eps ) )
// One block (256 threads) per row; 8 elements per thread held in registers for the
// two-pass (max, then sum-exp) logsumexp.
__global__ void softmin_kernel(const float* __restrict__ C,
                               const float* __restrict__ lw,
                               const float* __restrict__ potg,
                               const float* __restrict__ potold,
                               float* __restrict__ out,
                               float eps, float inv_eps, int blend) {
    __shared__ float g[NPTS];       // 8 KB staged weights
    __shared__ float redmax[8];
    __shared__ float redsum[8];

    int row = blockIdx.x;           // b*NPTS + n
    int b   = row >> 11;            // NPTS == 2048
    int tid = threadIdx.x;

    const float* lwb = lw + b * NPTS;
    if (potg) {
        const float* pg = potg + b * NPTS;
        for (int m = tid; m < NPTS; m += 256)
            g[m] = fmaf(pg[m], inv_eps, lwb[m]);
    } else {
        for (int m = tid; m < NPTS; m += 256)
            g[m] = lwb[m];
    }
    __syncthreads();

    const float* Crow = C + (size_t)row * NPTS;
    float v[8];
    float vmax = -1e30f;
#pragma unroll
    for (int k = 0; k < 8; k++) {
        int m = tid + k * 256;
        v[k]  = fmaf(Crow[m], -inv_eps, g[m]);
        vmax  = fmaxf(vmax, v[k]);
    }
#pragma unroll
    for (int o = 16; o; o >>= 1)
        vmax = fmaxf(vmax, __shfl_xor_sync(0xffffffffu, vmax, o));
    if ((tid & 31) == 0) redmax[tid >> 5] = vmax;
    __syncthreads();

    float bm = redmax[0];
#pragma unroll
    for (int i = 1; i < 8; i++) bm = fmaxf(bm, redmax[i]);

    float s = 0.f;
#pragma unroll
    for (int k = 0; k < 8; k++) s += __expf(v[k] - bm);
#pragma unroll
    for (int o = 16; o; o >>= 1)
        s += __shfl_xor_sync(0xffffffffu, s, o);
    if ((tid & 31) == 0) redsum[tid >> 5] = s;
    __syncthreads();

    if (tid == 0) {
        float tot = redsum[0];
#pragma unroll
        for (int i = 1; i < 8; i++) tot += redsum[i];
        float r = -eps * (bm + logf(tot));
        out[row] = blend ? 0.5f * (potold[row] + r) : r;
    }
}

// out[b] = sum_n alpha*(b_x - a_x) + sum_m beta*(a_y - b_y)   (double accumulation)
__global__ void loss_kernel(const float* __restrict__ alpha, const float* __restrict__ beta,
                            float* __restrict__ out) {
    __shared__ double red[8];
    int b = blockIdx.x, tid = threadIdx.x;
    double acc = 0.0;
    for (int i = tid; i < NPTS; i += 256) {
        int idx = b * NPTS + i;
        acc += (double)alpha[idx] * ((double)d_fin[3][idx] - (double)d_fin[0][idx]);
        acc += (double)beta[idx]  * ((double)d_fin[2][idx] - (double)d_fin[1][idx]);
    }
#pragma unroll
    for (int o = 16; o; o >>= 1)
        acc += __shfl_xor_sync(0xffffffffu, acc, o);
    if ((tid & 31) == 0) red[tid >> 5] = acc;
    __syncthreads();
    if (tid == 0) {
        double tot = red[0];
#pragma unroll
        for (int i = 1; i < 8; i++) tot += red[i];
        out[b] = (float)tot;
    }
}

// ---------------- host orchestration ----------------

extern "C" void kernel_launch(void* const* d_in, const int* in_sizes, int n_in,
                              void* d_out, int out_size) {
    const float* alpha = (const float*)d_in[0];
    const float* x     = (const float*)d_in[1];
    const float* beta  = (const float*)d_in[2];
    const float* y     = (const float*)d_in[3];
    float* out = (float*)d_out;

    float *C_, *pot_, *fin_, *la_, *lb_;
    cudaGetSymbolAddress((void**)&C_,   d_C);
    cudaGetSymbolAddress((void**)&pot_, d_pot);
    cudaGetSymbolAddress((void**)&fin_, d_fin);
    cudaGetSymbolAddress((void**)&la_,  d_la);
    cudaGetSymbolAddress((void**)&lb_,  d_lb);

    float* Cxx = C_ + 0 * CMAT;
    float* Cyy = C_ + 1 * CMAT;
    float* Cxy = C_ + 2 * CMAT;
    float* Cyx = C_ + 3 * CMAT;
    auto POT = [&](int buf, int j) { return pot_ + ((size_t)buf * 4 + j) * BN; };

    logw_kernel<<<(BN + 255) / 256, 256>>>(alpha, beta, la_, lb_);

    dim3 cg(NPTS / 256, NPTS, B);
    cost_kernel<<<cg, 256>>>(x, x, Cxx);
    cost_kernel<<<cg, 256>>>(y, y, Cyy);
    cost_kernel<<<cg, 256>>>(x, y, Cxy);
    cost_kernel<<<cg, 256>>>(y, x, Cyx);

    // geomloss epsilon schedule: [d^p] + exp(arange(p ln d, p ln blur, p ln s)) + [blur^p]
    const double eps_list[8] = {
        4.0, 3.9999999999999996, 1.0, 0.25, 0.0625, 0.015625, 0.00390625, 0.0025
    };

    // ---- init (eps = eps_list[0]) ----
    {
        float e = 4.0f, ie = 0.25f;
        softmin_kernel<<<BN, 256>>>(Cxx, la_, nullptr, nullptr, POT(0, 0), e, ie, 0); // a_x
        softmin_kernel<<<BN, 256>>>(Cyy, lb_, nullptr, nullptr, POT(0, 1), e, ie, 0); // b_y
        softmin_kernel<<<BN, 256>>>(Cyx, la_, nullptr, nullptr, POT(0, 2), e, ie, 0); // a_y
        softmin_kernel<<<BN, 256>>>(Cxy, lb_, nullptr, nullptr, POT(0, 3), e, ie, 0); // b_x
    }

    // ---- symmetrized annealed loop (tuple assignment => simultaneous updates) ----
    int cur = 0;
    for (int i = 0; i < 8; i++) {
        float e  = (float)eps_list[i];
        float ie = (float)(1.0 / eps_list[i]);
        int nxt = cur ^ 1;
        // at_x: Cxx, g = la + a_x/eps     -> blend into a_x
        softmin_kernel<<<BN, 256>>>(Cxx, la_, POT(cur, 0), POT(cur, 0), POT(nxt, 0), e, ie, 1);
        // bt_y: Cyy, g = lb + b_y/eps     -> blend into b_y
        softmin_kernel<<<BN, 256>>>(Cyy, lb_, POT(cur, 1), POT(cur, 1), POT(nxt, 1), e, ie, 1);
        // at_y: Cyx, g = la + b_x/eps     -> blend into a_y
        softmin_kernel<<<BN, 256>>>(Cyx, la_, POT(cur, 3), POT(cur, 2), POT(nxt, 2), e, ie, 1);
        // bt_x: Cxy, g = lb + a_y/eps     -> blend into b_x
        softmin_kernel<<<BN, 256>>>(Cxy, lb_, POT(cur, 2), POT(cur, 3), POT(nxt, 3), e, ie, 1);
        cur = nxt;
    }

    // ---- final extrapolation (eps = blur^p = 0.0025), SEQUENTIAL like the reference:
    //      b_x uses the freshly extrapolated a_y (fin2), not the loop's a_y.
    {
        float e = 0.0025f, ie = 400.0f;
        softmin_kernel<<<BN, 256>>>(Cxx, la_, POT(cur, 0), nullptr, fin_ + 0 * BN, e, ie, 0); // a_x
        softmin_kernel<<<BN, 256>>>(Cyy, lb_, POT(cur, 1), nullptr, fin_ + 1 * BN, e, ie, 0); // b_y
        softmin_kernel<<<BN, 256>>>(Cyx, la_, POT(cur, 3), nullptr, fin_ + 2 * BN, e, ie, 0); // a_y
        softmin_kernel<<<BN, 256>>>(Cxy, lb_, fin_ + 2 * BN, nullptr, fin_ + 3 * BN, e, ie, 0); // b_x (uses new a_y)
    }

    loss_kernel<<<B, 256>>>(alpha, beta, out);
}

// round 3
// speedup vs baseline: 2.6259x; 2.6259x over previous
#include <cuda_runtime.h>
#include <math.h>

#define B    8
#define NPTS 2048
#define BN   (B * NPTS)
#define CMAT ((size_t)B * NPTS * NPTS)

#define CMAX 1.5707964f                 // >= max possible cost (acos(clip)/2)
#define QSCL (65535.0f / CMAX)
#define DQ   (CMAX / 65535.0f)

// ---------------- scratch (allocation-free: __device__ globals) ----------------
// 0 = Cxx, 1 = Cyy, 2 = Cxy, 3 = Cyx (= Cxy^T, written by transpose fusion)
__device__ unsigned short d_C[4][B * NPTS * NPTS];   // 4 * 67 MB = 268 MB
__device__ float d_pot[2][4][BN];                    // ping-pong: a_x, b_y, a_y, b_x
__device__ float d_fin[4][BN];
__device__ float d_g[4][BN];                         // precomputed softmin weights
__device__ float d_la[BN];
__device__ float d_lb[BN];

// ---------------- helpers ----------------

// acos(clip(t))*0.5, quantized to uint16.  A&S 4.4.46 poly, |err| ~2e-8 << quant step.
__device__ __forceinline__ unsigned int qcost(float t) {
    t = fminf(fmaxf(t, -1.0f + 1e-6f), 1.0f - 1e-6f);
    float ax = fabsf(t);
    float s  = sqrtf(1.0f - ax);
    float p  = -0.0012624911f;
    p = fmaf(p, ax, 0.0066700901f);
    p = fmaf(p, ax, -0.0170881256f);
    p = fmaf(p, ax, 0.0308918810f);
    p = fmaf(p, ax, -0.0501743046f);
    p = fmaf(p, ax, 0.0889789874f);
    p = fmaf(p, ax, -0.2145988016f);
    p = fmaf(p, ax, 1.5707963050f);
    float r = s * p;
    float c = (t < 0.0f) ? (3.14159265359f - r) : r;
    return __float2uint_rn(c * 0.5f * QSCL);
}

// ---------------- kernels ----------------

__global__ void logw_kernel(const float* __restrict__ a, const float* __restrict__ bt,
                            float* __restrict__ la, float* __restrict__ lb) {
    int i = blockIdx.x * blockDim.x + threadIdx.x;
    if (i < BN) {
        float av = a[i];
        la[i] = (av > 0.f) ? logf(fmaxf(av, 1e-30f)) : -1e5f;
        float bv = bt[i];
        lb[i] = (bv > 0.f) ? logf(fmaxf(bv, 1e-30f)) : -1e5f;
    }
}

// Plain cost: each thread computes 2 adjacent m, packs into one uint store.
__global__ void cost_plain(const float* __restrict__ P, const float* __restrict__ Q,
                           unsigned short* __restrict__ C) {
    int m2 = blockIdx.x * blockDim.x + threadIdx.x;     // 0..1023 (pairs)
    int n  = blockIdx.y;
    int b  = blockIdx.z;
    const float* p = P + ((size_t)b * NPTS + n) * 3;
    float p0 = p[0], p1 = p[1], p2 = p[2];
    const float* q0 = Q + ((size_t)b * NPTS + m2 * 2) * 3;
    unsigned int lo = qcost(p0 * q0[0] + p1 * q0[1] + p2 * q0[2]);
    unsigned int hi = qcost(p0 * q0[3] + p1 * q0[4] + p2 * q0[5]);
    ((unsigned int*)C)[(((size_t)b * NPTS + n) * NPTS >> 1) + m2] = lo | (hi << 16);
}

// Fused Cxy + Cyx (transpose): 32x32 tiles, smem transpose for coalesced Cyx writes.
__global__ void cost_xy_kernel(const float* __restrict__ X, const float* __restrict__ Y,
                               unsigned short* __restrict__ Cxy,
                               unsigned short* __restrict__ Cyx) {
    __shared__ float xs[32][3], ys[32][3];
    __shared__ unsigned short t[32][33];
    int b  = blockIdx.z;
    int n0 = blockIdx.y * 32, m0 = blockIdx.x * 32;
    int tx = threadIdx.x, ty = threadIdx.y;
    int lt = ty * 32 + tx;
    if (lt < 96) {
        xs[lt / 3][lt % 3] = X[((size_t)b * NPTS + n0) * 3 + lt];
        ys[lt / 3][lt % 3] = Y[((size_t)b * NPTS + m0) * 3 + lt];
    }
    __syncthreads();
#pragma unroll
    for (int k = 0; k < 4; k++) {
        int nl = ty + 8 * k;
        float dot = xs[nl][0] * ys[tx][0] + xs[nl][1] * ys[tx][1] + xs[nl][2] * ys[tx][2];
        unsigned int q = qcost(dot);
        t[nl][tx] = (unsigned short)q;
        Cxy[((size_t)b * NPTS + n0 + nl) * NPTS + m0 + tx] = (unsigned short)q;
    }
    __syncthreads();
#pragma unroll
    for (int k = 0; k < 4; k++) {
        int ml = ty + 8 * k;
        Cyx[((size_t)b * NPTS + m0 + ml) * NPTS + n0 + tx] = t[tx][ml];
    }
}

// Precompute softmin weight vectors for one sinkhorn phase:
// g0 = la + a_x/eps, g1 = lb + b_y/eps, g2 = la + b_x/eps (at_y), g3 = lb + a_y/eps (bt_x)
__global__ void gprep4(const float* __restrict__ la, const float* __restrict__ lb,
                       const float* __restrict__ p0, const float* __restrict__ p1,
                       const float* __restrict__ p2, const float* __restrict__ p3,
                       float* __restrict__ g, float ie) {
    int i = blockIdx.x * blockDim.x + threadIdx.x;
    if (i < BN) {
        float lav = la[i], lbv = lb[i];
        g[0 * BN + i] = fmaf(p0[i], ie, lav);
        g[1 * BN + i] = fmaf(p1[i], ie, lbv);
        g[2 * BN + i] = fmaf(p3[i], ie, lav);
        g[3 * BN + i] = fmaf(p2[i], ie, lbv);
    }
}

__global__ void gprep1(const float* __restrict__ lw, const float* __restrict__ p,
                       float* __restrict__ gout, float ie) {
    int i = blockIdx.x * blockDim.x + threadIdx.x;
    if (i < BN) gout[i] = fmaf(p[i], ie, lw[i]);
}

// Softmin over uint16-quantized costs. 2 rows per block, 256 threads,
// 8 costs/thread/row via one uint4, weights via two float4 (L1/L2-hot).
__global__ void softmin2(const unsigned short* __restrict__ C,
                         const float* __restrict__ g,
                         const float* __restrict__ potold,
                         float* __restrict__ out,
                         float eps, float inv_eps, int blend) {
    __shared__ float rmax[2][8];
    __shared__ float rsum[2][8];

    int row0 = blockIdx.x * 2;
    int b    = row0 >> 11;                  // NPTS == 2048
    int tid  = threadIdx.x;

    const float4* gb = (const float4*)(g + (size_t)b * NPTS);
    float4 ga = gb[tid * 2];
    float4 gc = gb[tid * 2 + 1];

    uint4 q0 = ((const uint4*)(C + (size_t)row0 * NPTS))[tid];
    uint4 q1 = ((const uint4*)(C + (size_t)(row0 + 1) * NPTS))[tid];

    float dq = DQ * inv_eps;
    float v0[8], v1[8];
    v0[0] = fmaf((float)(q0.x & 0xffff), -dq, ga.x);
    v0[1] = fmaf((float)(q0.x >> 16),    -dq, ga.y);
    v0[2] = fmaf((float)(q0.y & 0xffff), -dq, ga.z);
    v0[3] = fmaf((float)(q0.y >> 16),    -dq, ga.w);
    v0[4] = fmaf((float)(q0.z & 0xffff), -dq, gc.x);
    v0[5] = fmaf((float)(q0.z >> 16),    -dq, gc.y);
    v0[6] = fmaf((float)(q0.w & 0xffff), -dq, gc.z);
    v0[7] = fmaf((float)(q0.w >> 16),    -dq, gc.w);
    v1[0] = fmaf((float)(q1.x & 0xffff), -dq, ga.x);
    v1[1] = fmaf((float)(q1.x >> 16),    -dq, ga.y);
    v1[2] = fmaf((float)(q1.y & 0xffff), -dq, ga.z);
    v1[3] = fmaf((float)(q1.y >> 16),    -dq, ga.w);
    v1[4] = fmaf((float)(q1.z & 0xffff), -dq, gc.x);
    v1[5] = fmaf((float)(q1.z >> 16),    -dq, gc.y);
    v1[6] = fmaf((float)(q1.w & 0xffff), -dq, gc.z);
    v1[7] = fmaf((float)(q1.w >> 16),    -dq, gc.w);

    float m0 = v0[0], m1 = v1[0];
#pragma unroll
    for (int k = 1; k < 8; k++) { m0 = fmaxf(m0, v0[k]); m1 = fmaxf(m1, v1[k]); }
#pragma unroll
    for (int o = 16; o; o >>= 1) {
        m0 = fmaxf(m0, __shfl_xor_sync(0xffffffffu, m0, o));
        m1 = fmaxf(m1, __shfl_xor_sync(0xffffffffu, m1, o));
    }
    if ((tid & 31) == 0) { rmax[0][tid >> 5] = m0; rmax[1][tid >> 5] = m1; }
    __syncthreads();

    float bm0 = rmax[0][0], bm1 = rmax[1][0];
#pragma unroll
    for (int i = 1; i < 8; i++) { bm0 = fmaxf(bm0, rmax[0][i]); bm1 = fmaxf(bm1, rmax[1][i]); }

    float s0 = 0.f, s1 = 0.f;
#pragma unroll
    for (int k = 0; k < 8; k++) { s0 += __expf(v0[k] - bm0); s1 += __expf(v1[k] - bm1); }
#pragma unroll
    for (int o = 16; o; o >>= 1) {
        s0 += __shfl_xor_sync(0xffffffffu, s0, o);
        s1 += __shfl_xor_sync(0xffffffffu, s1, o);
    }
    if ((tid & 31) == 0) { rsum[0][tid >> 5] = s0; rsum[1][tid >> 5] = s1; }
    __syncthreads();

    if (tid == 0) {
        float t0 = rsum[0][0], t1 = rsum[1][0];
#pragma unroll
        for (int i = 1; i < 8; i++) { t0 += rsum[0][i]; t1 += rsum[1][i]; }
        float r0 = -eps * (bm0 + logf(t0));
        float r1 = -eps * (bm1 + logf(t1));
        if (blend) {
            out[row0]     = 0.5f * (potold[row0]     + r0);
            out[row0 + 1] = 0.5f * (potold[row0 + 1] + r1);
        } else {
            out[row0]     = r0;
            out[row0 + 1] = r1;
        }
    }
}

// out[b] = sum_n alpha*(b_x - a_x) + sum_m beta*(a_y - b_y)   (double accumulation)
__global__ void loss_kernel(const float* __restrict__ alpha, const float* __restrict__ beta,
                            float* __restrict__ out) {
    __shared__ double red[8];
    int b = blockIdx.x, tid = threadIdx.x;
    double acc = 0.0;
    for (int i = tid; i < NPTS; i += 256) {
        int idx = b * NPTS + i;
        acc += (double)alpha[idx] * ((double)d_fin[3][idx] - (double)d_fin[0][idx]);
        acc += (double)beta[idx]  * ((double)d_fin[2][idx] - (double)d_fin[1][idx]);
    }
#pragma unroll
    for (int o = 16; o; o >>= 1)
        acc += __shfl_xor_sync(0xffffffffu, acc, o);
    if ((tid & 31) == 0) red[tid >> 5] = acc;
    __syncthreads();
    if (tid == 0) {
        double tot = red[0];
#pragma unroll
        for (int i = 1; i < 8; i++) tot += red[i];
        out[b] = (float)tot;
    }
}

// ---------------- host orchestration ----------------

extern "C" void kernel_launch(void* const* d_in, const int* in_sizes, int n_in,
                              void* d_out, int out_size) {
    const float* alpha = (const float*)d_in[0];
    const float* x     = (const float*)d_in[1];
    const float* beta  = (const float*)d_in[2];
    const float* y     = (const float*)d_in[3];
    float* out = (float*)d_out;

    unsigned short* C_;
    float *pot_, *fin_, *g_, *la_, *lb_;
    cudaGetSymbolAddress((void**)&C_,   d_C);
    cudaGetSymbolAddress((void**)&pot_, d_pot);
    cudaGetSymbolAddress((void**)&fin_, d_fin);
    cudaGetSymbolAddress((void**)&g_,   d_g);
    cudaGetSymbolAddress((void**)&la_,  d_la);
    cudaGetSymbolAddress((void**)&lb_,  d_lb);

    unsigned short* Cxx = C_ + 0 * CMAT;
    unsigned short* Cyy = C_ + 1 * CMAT;
    unsigned short* Cxy = C_ + 2 * CMAT;
    unsigned short* Cyx = C_ + 3 * CMAT;
    auto POT = [&](int buf, int j) { return pot_ + ((size_t)buf * 4 + j) * BN; };

    logw_kernel<<<(BN + 255) / 256, 256>>>(alpha, beta, la_, lb_);

    dim3 cp(NPTS / 512, NPTS, B);
    cost_plain<<<cp, 256>>>(x, x, Cxx);
    cost_plain<<<cp, 256>>>(y, y, Cyy);
    dim3 ct(NPTS / 32, NPTS / 32, B);
    cost_xy_kernel<<<ct, dim3(32, 8)>>>(x, y, Cxy, Cyx);

    const double eps_list[8] = {
        4.0, 3.9999999999999996, 1.0, 0.25, 0.0625, 0.015625, 0.00390625, 0.0025
    };

    const int SMG = BN;   // 8192 blocks (2 rows each)

    // ---- init (eps = eps_list[0]): weights are just la / lb ----
    {
        float e = 4.0f, ie = 0.25f;
        softmin2<<<SMG / 2, 256>>>(Cxx, la_, nullptr, POT(0, 0), e, ie, 0); // a_x
        softmin2<<<SMG / 2, 256>>>(Cyy, lb_, nullptr, POT(0, 1), e, ie, 0); // b_y
        softmin2<<<SMG / 2, 256>>>(Cyx, la_, nullptr, POT(0, 2), e, ie, 0); // a_y
        softmin2<<<SMG / 2, 256>>>(Cxy, lb_, nullptr, POT(0, 3), e, ie, 0); // b_x
    }

    // ---- symmetrized annealed loop (simultaneous updates via ping-pong) ----
    int cur = 0;
    for (int i = 0; i < 8; i++) {
        float e  = (float)eps_list[i];
        float ie = (float)(1.0 / eps_list[i]);
        int nxt = cur ^ 1;
        gprep4<<<(BN + 255) / 256, 256>>>(la_, lb_, POT(cur, 0), POT(cur, 1),
                                          POT(cur, 2), POT(cur, 3), g_, ie);
        softmin2<<<SMG / 2, 256>>>(Cxx, g_ + 0 * BN, POT(cur, 0), POT(nxt, 0), e, ie, 1);
        softmin2<<<SMG / 2, 256>>>(Cyy, g_ + 1 * BN, POT(cur, 1), POT(nxt, 1), e, ie, 1);
        softmin2<<<SMG / 2, 256>>>(Cyx, g_ + 2 * BN, POT(cur, 2), POT(nxt, 2), e, ie, 1);
        softmin2<<<SMG / 2, 256>>>(Cxy, g_ + 3 * BN, POT(cur, 3), POT(nxt, 3), e, ie, 1);
        cur = nxt;
    }

    // ---- final extrapolation (eps = blur^p = 0.0025), SEQUENTIAL like reference:
    //      b_x uses the freshly extrapolated a_y.
    {
        float e = 0.0025f, ie = 400.0f;
        gprep4<<<(BN + 255) / 256, 256>>>(la_, lb_, POT(cur, 0), POT(cur, 1),
                                          POT(cur, 2), POT(cur, 3), g_, ie);
        softmin2<<<SMG / 2, 256>>>(Cxx, g_ + 0 * BN, nullptr, fin_ + 0 * BN, e, ie, 0); // a_x
        softmin2<<<SMG / 2, 256>>>(Cyy, g_ + 1 * BN, nullptr, fin_ + 1 * BN, e, ie, 0); // b_y
        softmin2<<<SMG / 2, 256>>>(Cyx, g_ + 2 * BN, nullptr, fin_ + 2 * BN, e, ie, 0); // a_y
        gprep1<<<(BN + 255) / 256, 256>>>(lb_, fin_ + 2 * BN, g_ + 3 * BN, ie);
        softmin2<<<SMG / 2, 256>>>(Cxy, g_ + 3 * BN, nullptr, fin_ + 3 * BN, e, ie, 0); // b_x
    }

    loss_kernel<<<B, 256>>>(alpha, beta, out);
}

// round 5
// speedup vs baseline: 2.7247x; 1.0376x over previous
#include <cuda_runtime.h>
#include <math.h>

#define B    8
#define NPTS 2048
#define BN   (B * NPTS)
#define CMAT ((size_t)B * NPTS * NPTS)

#define CMAX  1.5707964f
#define QSCL  (65535.0f / CMAX)
#define DQ    (1.5707964 / 65535.0)            // double, host-side scaling
#define LOG2E 1.4426950408889634
#define LN2   0.6931471805599453

// ---------------- scratch (allocation-free: __device__ globals) ----------------
__device__ unsigned short d_C[4][B * NPTS * NPTS];   // Cxx, Cyy, Cxy, Cyx
__device__ float d_pot[2][4][BN];                    // ping-pong: a_x, b_y, a_y, b_x
__device__ float d_fin[4][BN];
__device__ float d_g[2][4][BN];                      // DOUBLE-BUFFERED weight vectors
__device__ float d_la[BN];                           // log2e * log(alpha)
__device__ float d_lb[BN];                           // log2e * log(beta)

// ---------------- helpers ----------------

// acos(clip(t))*0.5 quantized to uint16. A&S 4.4.46 poly, |err| ~2e-8 << quant step.
__device__ __forceinline__ unsigned int qcost(float t) {
    t = fminf(fmaxf(t, -1.0f + 1e-6f), 1.0f - 1e-6f);
    float ax = fabsf(t);
    float s  = sqrtf(1.0f - ax);
    float p  = -0.0012624911f;
    p = fmaf(p, ax, 0.0066700901f);
    p = fmaf(p, ax, -0.0170881256f);
    p = fmaf(p, ax, 0.0308918810f);
    p = fmaf(p, ax, -0.0501743046f);
    p = fmaf(p, ax, 0.0889789874f);
    p = fmaf(p, ax, -0.2145988016f);
    p = fmaf(p, ax, 1.5707963050f);
    float r = s * p;
    float c = (t < 0.0f) ? (3.14159265359f - r) : r;
    return __float2uint_rn(c * 0.5f * QSCL);
}

// ---------------- kernels ----------------

__global__ void logw_kernel(const float* __restrict__ a, const float* __restrict__ bt,
                            float* __restrict__ la, float* __restrict__ lb) {
    int i = blockIdx.x * blockDim.x + threadIdx.x;
    if (i < BN) {
        float av = a[i];
        la[i] = (float)LOG2E * ((av > 0.f) ? logf(fmaxf(av, 1e-30f)) : -1e5f);
        float bv = bt[i];
        lb[i] = (float)LOG2E * ((bv > 0.f) ? logf(fmaxf(bv, 1e-30f)) : -1e5f);
    }
}

// Tiled cost with fused transpose write. tri=1: symmetric mode (skip lower tiles,
// write tile + transposed tile into the SAME matrix).
__global__ void cost_xy_kernel(const float* __restrict__ X, const float* __restrict__ Y,
                               unsigned short* __restrict__ Cxy,
                               unsigned short* __restrict__ Cyx, int tri) {
    if (tri && (int)blockIdx.x < (int)blockIdx.y) return;   // keep m0 >= n0
    __shared__ float xs[32][3], ys[32][3];
    __shared__ unsigned short t[32][33];
    int b  = blockIdx.z;
    int n0 = blockIdx.y * 32, m0 = blockIdx.x * 32;
    int tx = threadIdx.x, ty = threadIdx.y;
    int lt = ty * 32 + tx;
    if (lt < 96) {
        xs[lt / 3][lt % 3] = X[((size_t)b * NPTS + n0) * 3 + lt];
        ys[lt / 3][lt % 3] = Y[((size_t)b * NPTS + m0) * 3 + lt];
    }
    __syncthreads();
#pragma unroll
    for (int k = 0; k < 4; k++) {
        int nl = ty + 8 * k;
        float dot = xs[nl][0] * ys[tx][0] + xs[nl][1] * ys[tx][1] + xs[nl][2] * ys[tx][2];
        unsigned int q = qcost(dot);
        t[nl][tx] = (unsigned short)q;
        Cxy[((size_t)b * NPTS + n0 + nl) * NPTS + m0 + tx] = (unsigned short)q;
    }
    __syncthreads();
#pragma unroll
    for (int k = 0; k < 4; k++) {
        int ml = ty + 8 * k;
        Cyx[((size_t)b * NPTS + m0 + ml) * NPTS + n0 + tx] = t[tx][ml];
    }
}

// ---- fused softmin: grid.y selects job; 1 warp per half-row; 4 rows/block ----
struct SmJobs {
    const unsigned short* C[4];
    const float*          gin[4];     // log2-scaled weight vector (per-batch indexed)
    const float*          potold[4];  // blend source (may be null)
    float*                out[4];
    float*                gout[4];    // next-phase weight write (OTHER bank; may be null)
    const float*          lw[4];      // log2-scaled log-weights for gout
};

__global__ void __launch_bounds__(256) softmin_fused(
        SmJobs J, float dqs, float negeln2, float ienl2, int blend) {
    __shared__ float sm_m[4][2];
    __shared__ float sm_s[4][2];

    int tid  = threadIdx.x;
    int warp = tid >> 5, lane = tid & 31;
    int rloc = warp >> 1, half = warp & 1;
    int row  = blockIdx.x * 4 + rloc;
    int job  = blockIdx.y;
    int b    = row >> 11;                       // NPTS == 2048

    const unsigned short* Crow = J.C[job] + (size_t)row * NPTS + half * 1024;
    const float*          g    = J.gin[job] + b * NPTS + half * 1024;
    const uint4*  Cq = (const uint4*)Crow;
    const float4* gq = (const float4*)g;

    float v[32];
    float m = -1e30f;
#pragma unroll
    for (int k = 0; k < 4; k++) {
        int i = lane + 32 * k;
        uint4  q  = Cq[i];
        float4 gA = gq[2 * i];
        float4 gB = gq[2 * i + 1];
        v[8 * k + 0] = fmaf((float)(q.x & 0xffff), -dqs, gA.x);
        v[8 * k + 1] = fmaf((float)(q.x >> 16),    -dqs, gA.y);
        v[8 * k + 2] = fmaf((float)(q.y & 0xffff), -dqs, gA.z);
        v[8 * k + 3] = fmaf((float)(q.y >> 16),    -dqs, gA.w);
        v[8 * k + 4] = fmaf((float)(q.z & 0xffff), -dqs, gB.x);
        v[8 * k + 5] = fmaf((float)(q.z >> 16),    -dqs, gB.y);
        v[8 * k + 6] = fmaf((float)(q.w & 0xffff), -dqs, gB.z);
        v[8 * k + 7] = fmaf((float)(q.w >> 16),    -dqs, gB.w);
    }
#pragma unroll
    for (int k = 0; k < 32; k++) m = fmaxf(m, v[k]);
#pragma unroll
    for (int o = 16; o; o >>= 1) m = fmaxf(m, __shfl_xor_sync(0xffffffffu, m, o));
    if (lane == 0) sm_m[rloc][half] = m;
    __syncthreads();

    float bm = fmaxf(sm_m[rloc][0], sm_m[rloc][1]);
    float s = 0.f;
#pragma unroll
    for (int k = 0; k < 32; k++) s += exp2f(v[k] - bm);
#pragma unroll
    for (int o = 16; o; o >>= 1) s += __shfl_xor_sync(0xffffffffu, s, o);
    if (lane == 0) sm_s[rloc][half] = s;
    __syncthreads();

    if (half == 0 && lane == 0) {
        float tot = sm_s[rloc][0] + sm_s[rloc][1];
        float r = negeln2 * (bm + log2f(tot));      // -eps*ln2*(bm2+log2 sum)
        if (blend) r = 0.5f * (J.potold[job][row] + r);
        J.out[job][row] = r;
        if (J.gout[job])
            J.gout[job][row] = fmaf(r, ienl2, J.lw[job][row]);  // log2e*(lw + r/eps')
    }
}

// out[b] = sum_n alpha*(b_x - a_x) + sum_m beta*(a_y - b_y)   (double accumulation)
__global__ void loss_kernel(const float* __restrict__ alpha, const float* __restrict__ beta,
                            float* __restrict__ out) {
    __shared__ double red[8];
    int b = blockIdx.x, tid = threadIdx.x;
    double acc = 0.0;
    for (int i = tid; i < NPTS; i += 256) {
        int idx = b * NPTS + i;
        acc += (double)alpha[idx] * ((double)d_fin[3][idx] - (double)d_fin[0][idx]);
        acc += (double)beta[idx]  * ((double)d_fin[2][idx] - (double)d_fin[1][idx]);
    }
#pragma unroll
    for (int o = 16; o; o >>= 1)
        acc += __shfl_xor_sync(0xffffffffu, acc, o);
    if ((tid & 31) == 0) red[tid >> 5] = acc;
    __syncthreads();
    if (tid == 0) {
        double tot = red[0];
#pragma unroll
        for (int i = 1; i < 8; i++) tot += red[i];
        out[b] = (float)tot;
    }
}

// ---------------- host orchestration ----------------

extern "C" void kernel_launch(void* const* d_in, const int* in_sizes, int n_in,
                              void* d_out, int out_size) {
    const float* alpha = (const float*)d_in[0];
    const float* x     = (const float*)d_in[1];
    const float* beta  = (const float*)d_in[2];
    const float* y     = (const float*)d_in[3];
    float* out = (float*)d_out;

    unsigned short* C_;
    float *pot_, *fin_, *g_, *la_, *lb_;
    cudaGetSymbolAddress((void**)&C_,   d_C);
    cudaGetSymbolAddress((void**)&pot_, d_pot);
    cudaGetSymbolAddress((void**)&fin_, d_fin);
    cudaGetSymbolAddress((void**)&g_,   d_g);
    cudaGetSymbolAddress((void**)&la_,  d_la);
    cudaGetSymbolAddress((void**)&lb_,  d_lb);

    unsigned short* Cxx = C_ + 0 * CMAT;
    unsigned short* Cyy = C_ + 1 * CMAT;
    unsigned short* Cxy = C_ + 2 * CMAT;
    unsigned short* Cyx = C_ + 3 * CMAT;
    auto POT = [&](int buf, int j) { return pot_ + ((size_t)buf * 4 + j) * BN; };
    auto G   = [&](int bank, int j) { return g_ + ((size_t)bank * 4 + j) * BN; };

    logw_kernel<<<(BN + 255) / 256, 256>>>(alpha, beta, la_, lb_);

    dim3 ct(NPTS / 32, NPTS / 32, B);
    cost_xy_kernel<<<ct, dim3(32, 8)>>>(x, x, Cxx, Cxx, 1);   // symmetric
    cost_xy_kernel<<<ct, dim3(32, 8)>>>(y, y, Cyy, Cyy, 1);   // symmetric
    cost_xy_kernel<<<ct, dim3(32, 8)>>>(x, y, Cxy, Cyx, 0);

    const double eps_list[8] = {
        4.0, 3.9999999999999996, 1.0, 0.25, 0.0625, 0.015625, 0.00390625, 0.0025
    };

    const unsigned short* CJ[4] = {Cxx, Cyy, Cyx, Cxy};
    // job j: j0=a_x(g0), j1=b_y(g1), j2=a_y (reads g2=la+b_x/e, writes g3=lb+a_y/e'),
    //        j3=b_x (reads g3=lb+a_y/e, writes g2=la+b_x/e')
    const int GOUTI[4] = {0, 1, 3, 2};
    const float* LW[4] = {la_, lb_, lb_, la_};

    dim3 smg(BN / 4, 4);

    // ---- init (eps = 4): gin = raw log-weights, gout -> bank 0 ----
    {
        double eps = 4.0, eps_next = eps_list[0];
        SmJobs J;
        for (int j = 0; j < 4; j++) {
            J.C[j] = CJ[j];
            J.gin[j] = (j == 0 || j == 2) ? la_ : lb_;
            J.potold[j] = nullptr;
            J.out[j] = POT(0, j);
            J.gout[j] = G(0, GOUTI[j]);
            J.lw[j] = LW[j];
        }
        softmin_fused<<<smg, 256>>>(J, (float)(DQ * LOG2E / eps),
                                    (float)(-eps * LN2),
                                    (float)(LOG2E / eps_next), 0);
    }

    // ---- symmetrized annealed loop: gin bank gb, gout bank gb^1 (no aliasing) ----
    int cur = 0, gb = 0;
    for (int i = 0; i < 8; i++) {
        double eps = eps_list[i];
        double eps_next = (i < 7) ? eps_list[i + 1] : 0.0025;   // final also blur^p
        int nxt = cur ^ 1;
        SmJobs J;
        for (int j = 0; j < 4; j++) {
            J.C[j] = CJ[j];
            J.gin[j] = G(gb, j);
            J.potold[j] = POT(cur, j);
            J.out[j] = POT(nxt, j);
            J.gout[j] = G(gb ^ 1, GOUTI[j]);
            J.lw[j] = LW[j];
        }
        softmin_fused<<<smg, 256>>>(J, (float)(DQ * LOG2E / eps),
                                    (float)(-eps * LN2),
                                    (float)(LOG2E / eps_next), 1);
        cur = nxt;
        gb ^= 1;
    }

    // ---- final extrapolation (eps = 0.0025), SEQUENTIAL: b_x uses fresh a_y ----
    {
        double eps = 0.0025;
        float dqs = (float)(DQ * LOG2E / eps);
        float nel = (float)(-eps * LN2);
        float ien = (float)(LOG2E / eps);
        SmJobs J;
        for (int j = 0; j < 3; j++) {
            J.C[j] = CJ[j];
            J.gin[j] = G(gb, j);
            J.potold[j] = nullptr;
            J.out[j] = fin_ + (size_t)j * BN;
            J.gout[j] = (j == 2) ? G(gb ^ 1, 3) : nullptr;  // fresh a_y -> other bank g3
            J.lw[j] = LW[j];
        }
        J.C[3] = CJ[3]; J.gin[3] = G(gb, 3); J.potold[3] = nullptr;
        J.out[3] = fin_ + 3 * (size_t)BN; J.gout[3] = nullptr; J.lw[3] = LW[3];
        softmin_fused<<<dim3(BN / 4, 3), 256>>>(J, dqs, nel, ien, 0);

        // b_x alone, reading the freshly written g3 from the other bank
        SmJobs J2;
        J2.C[0] = Cxy; J2.gin[0] = G(gb ^ 1, 3); J2.potold[0] = nullptr;
        J2.out[0] = fin_ + 3 * (size_t)BN; J2.gout[0] = nullptr; J2.lw[0] = lb_;
        softmin_fused<<<dim3(BN / 4, 1), 256>>>(J2, dqs, nel, ien, 0);
    }

    loss_kernel<<<B, 256>>>(alpha, beta, out);
}

// round 6
// speedup vs baseline: 2.7969x; 1.0265x over previous
#include <cuda_runtime.h>
#include <cuda_fp16.h>
#include <math.h>

#define B    8
#define NPTS 2048
#define BN   (B * NPTS)
#define CMAT ((size_t)B * NPTS * NPTS)

#define CMAX  1.5707964f
#define QSCL  (65535.0f / CMAX)
#define DQ    (1.5707964 / 65535.0)
#define LOG2E 1.4426950408889634
#define LN2   0.6931471805599453

// ---------------- scratch ----------------
__device__ unsigned short d_C[4][B * NPTS * NPTS];   // Cxx, Cyy, Cxy, Cyx
__device__ float d_pot[2][4][BN];
__device__ float d_fin[4][BN];
__device__ float d_g[2][4][BN];                      // double-buffered weights
__device__ float d_la[BN];                           // log2e * log(alpha)
__device__ float d_lb[BN];

// ---------------- helpers ----------------
__device__ __forceinline__ unsigned int qcost(float t) {
    t = fminf(fmaxf(t, -1.0f + 1e-6f), 1.0f - 1e-6f);
    float ax = fabsf(t);
    float s  = sqrtf(1.0f - ax);
    float p  = -0.0012624911f;
    p = fmaf(p, ax, 0.0066700901f);
    p = fmaf(p, ax, -0.0170881256f);
    p = fmaf(p, ax, 0.0308918810f);
    p = fmaf(p, ax, -0.0501743046f);
    p = fmaf(p, ax, 0.0889789874f);
    p = fmaf(p, ax, -0.2145988016f);
    p = fmaf(p, ax, 1.5707963050f);
    float r = s * p;
    float c = (t < 0.0f) ? (3.14159265359f - r) : r;
    return __float2uint_rn(c * 0.5f * QSCL);
}

// ---------------- kernels ----------------
__global__ void logw_kernel(const float* __restrict__ a, const float* __restrict__ bt,
                            float* __restrict__ la, float* __restrict__ lb) {
    int i = blockIdx.x * blockDim.x + threadIdx.x;
    if (i < BN) {
        float av = a[i];
        la[i] = (float)LOG2E * ((av > 0.f) ? logf(fmaxf(av, 1e-30f)) : -1e5f);
        float bv = bt[i];
        lb[i] = (float)LOG2E * ((bv > 0.f) ? logf(fmaxf(bv, 1e-30f)) : -1e5f);
    }
}

// All three cost jobs in one launch: z = job*8 + batch.
// job 0: Cxx (symmetric/tri), job 1: Cyy (tri), job 2: Cxy + Cyx.
__global__ void cost_all(const float* __restrict__ x, const float* __restrict__ y,
                         unsigned short* __restrict__ Cxx, unsigned short* __restrict__ Cyy,
                         unsigned short* __restrict__ Cxy, unsigned short* __restrict__ Cyx) {
    int job = blockIdx.z >> 3;
    int b   = blockIdx.z & 7;
    const float *P, *Q;
    unsigned short *Co, *Ct;
    int tri;
    if (job == 0)      { P = x; Q = x; Co = Cxx; Ct = Cxx; tri = 1; }
    else if (job == 1) { P = y; Q = y; Co = Cyy; Ct = Cyy; tri = 1; }
    else               { P = x; Q = y; Co = Cxy; Ct = Cyx; tri = 0; }
    if (tri && (int)blockIdx.x < (int)blockIdx.y) return;

    __shared__ float xs[32][3], ys[32][3];
    __shared__ unsigned short t[32][33];
    int n0 = blockIdx.y * 32, m0 = blockIdx.x * 32;
    int tx = threadIdx.x, ty = threadIdx.y;
    int lt = ty * 32 + tx;
    if (lt < 96) {
        xs[lt / 3][lt % 3] = P[((size_t)b * NPTS + n0) * 3 + lt];
        ys[lt / 3][lt % 3] = Q[((size_t)b * NPTS + m0) * 3 + lt];
    }
    __syncthreads();
#pragma unroll
    for (int k = 0; k < 4; k++) {
        int nl = ty + 8 * k;
        float dot = xs[nl][0] * ys[tx][0] + xs[nl][1] * ys[tx][1] + xs[nl][2] * ys[tx][2];
        unsigned int q = qcost(dot);
        t[nl][tx] = (unsigned short)q;
        Co[((size_t)b * NPTS + n0 + nl) * NPTS + m0 + tx] = (unsigned short)q;
    }
    __syncthreads();
#pragma unroll
    for (int k = 0; k < 4; k++) {
        int ml = ty + 8 * k;
        Ct[((size_t)b * NPTS + m0 + ml) * NPTS + n0 + tx] = t[tx][ml];
    }
}

// ---- fused softmin: grid.y selects job; 1 warp per half-row; 4 rows/block ----
struct SmJobs {
    const unsigned short* C[4];
    const float*          gin[4];
    const float*          potold[4];
    float*                out[4];
    float*                gout[4];
    const float*          lw[4];
};

template <bool HEXP>
__global__ void __launch_bounds__(256) softmin_fused(
        SmJobs J, float dqs, float negeln2, float ienl2, int blend) {
    __shared__ float sm_m[4][2];
    __shared__ float sm_s[4][2];

    int tid  = threadIdx.x;
    int warp = tid >> 5, lane = tid & 31;
    int rloc = warp >> 1, half = warp & 1;
    int row  = blockIdx.x * 4 + rloc;
    int job  = blockIdx.y;
    int b    = row >> 11;

    const unsigned short* Crow = J.C[job] + (size_t)row * NPTS + half * 1024;
    const float*          g    = J.gin[job] + b * NPTS + half * 1024;
    const uint4*  Cq = (const uint4*)Crow;
    const float4* gq = (const float4*)g;

    float v[32];
    float m = -1e30f;
#pragma unroll
    for (int k = 0; k < 4; k++) {
        int i = lane + 32 * k;
        uint4  q  = __ldcs(Cq + i);
        float4 gA = gq[2 * i];
        float4 gB = gq[2 * i + 1];
        v[8 * k + 0] = fmaf((float)(q.x & 0xffff), -dqs, gA.x);
        v[8 * k + 1] = fmaf((float)(q.x >> 16),    -dqs, gA.y);
        v[8 * k + 2] = fmaf((float)(q.y & 0xffff), -dqs, gA.z);
        v[8 * k + 3] = fmaf((float)(q.y >> 16),    -dqs, gA.w);
        v[8 * k + 4] = fmaf((float)(q.z & 0xffff), -dqs, gB.x);
        v[8 * k + 5] = fmaf((float)(q.z >> 16),    -dqs, gB.y);
        v[8 * k + 6] = fmaf((float)(q.w & 0xffff), -dqs, gB.z);
        v[8 * k + 7] = fmaf((float)(q.w >> 16),    -dqs, gB.w);
    }
#pragma unroll
    for (int k = 0; k < 32; k++) m = fmaxf(m, v[k]);
#pragma unroll
    for (int o = 16; o; o >>= 1) m = fmaxf(m, __shfl_xor_sync(0xffffffffu, m, o));
    if (lane == 0) sm_m[rloc][half] = m;
    __syncthreads();

    float bm = fmaxf(sm_m[rloc][0], sm_m[rloc][1]);
    float s;
    if (HEXP) {
        // f16x2 MUFU.EX2 at 2 values/op; 4 rotating half2 accumulators
        // (<=4 adds per half lane-sum) then exact fp32 finish.
        __half2 a0 = __float2half2_rn(0.f), a1 = a0, a2 = a0, a3 = a0;
#pragma unroll
        for (int k = 0; k < 32; k += 8) {
            a0 = __hadd2(a0, h2exp2(__floats2half2_rn(v[k + 0] - bm, v[k + 1] - bm)));
            a1 = __hadd2(a1, h2exp2(__floats2half2_rn(v[k + 2] - bm, v[k + 3] - bm)));
            a2 = __hadd2(a2, h2exp2(__floats2half2_rn(v[k + 4] - bm, v[k + 5] - bm)));
            a3 = __hadd2(a3, h2exp2(__floats2half2_rn(v[k + 6] - bm, v[k + 7] - bm)));
        }
        float2 f0 = __half22float2(a0), f1 = __half22float2(a1);
        float2 f2 = __half22float2(a2), f3 = __half22float2(a3);
        s = ((f0.x + f0.y) + (f1.x + f1.y)) + ((f2.x + f2.y) + (f3.x + f3.y));
    } else {
        s = 0.f;
#pragma unroll
        for (int k = 0; k < 32; k++) s += exp2f(v[k] - bm);
    }
#pragma unroll
    for (int o = 16; o; o >>= 1) s += __shfl_xor_sync(0xffffffffu, s, o);
    if (lane == 0) sm_s[rloc][half] = s;
    __syncthreads();

    if (half == 0 && lane == 0) {
        float tot = sm_s[rloc][0] + sm_s[rloc][1];
        float r = negeln2 * (bm + log2f(tot));
        if (blend) r = 0.5f * (J.potold[job][row] + r);
        J.out[job][row] = r;
        if (J.gout[job])
            J.gout[job][row] = fmaf(r, ienl2, J.lw[job][row]);
    }
}

__global__ void loss_kernel(const float* __restrict__ alpha, const float* __restrict__ beta,
                            float* __restrict__ out) {
    __shared__ double red[8];
    int b = blockIdx.x, tid = threadIdx.x;
    double acc = 0.0;
    for (int i = tid; i < NPTS; i += 256) {
        int idx = b * NPTS + i;
        acc += (double)alpha[idx] * ((double)d_fin[3][idx] - (double)d_fin[0][idx]);
        acc += (double)beta[idx]  * ((double)d_fin[2][idx] - (double)d_fin[1][idx]);
    }
#pragma unroll
    for (int o = 16; o; o >>= 1)
        acc += __shfl_xor_sync(0xffffffffu, acc, o);
    if ((tid & 31) == 0) red[tid >> 5] = acc;
    __syncthreads();
    if (tid == 0) {
        double tot = red[0];
#pragma unroll
        for (int i = 1; i < 8; i++) tot += red[i];
        out[b] = (float)tot;
    }
}

// ---------------- host orchestration ----------------
extern "C" void kernel_launch(void* const* d_in, const int* in_sizes, int n_in,
                              void* d_out, int out_size) {
    const float* alpha = (const float*)d_in[0];
    const float* x     = (const float*)d_in[1];
    const float* beta  = (const float*)d_in[2];
    const float* y     = (const float*)d_in[3];
    float* out = (float*)d_out;

    unsigned short* C_;
    float *pot_, *fin_, *g_, *la_, *lb_;
    cudaGetSymbolAddress((void**)&C_,   d_C);
    cudaGetSymbolAddress((void**)&pot_, d_pot);
    cudaGetSymbolAddress((void**)&fin_, d_fin);
    cudaGetSymbolAddress((void**)&g_,   d_g);
    cudaGetSymbolAddress((void**)&la_,  d_la);
    cudaGetSymbolAddress((void**)&lb_,  d_lb);

    unsigned short* Cxx = C_ + 0 * CMAT;
    unsigned short* Cyy = C_ + 1 * CMAT;
    unsigned short* Cxy = C_ + 2 * CMAT;
    unsigned short* Cyx = C_ + 3 * CMAT;
    auto POT = [&](int buf, int j) { return pot_ + ((size_t)buf * 4 + j) * BN; };
    auto G   = [&](int bank, int j) { return g_ + ((size_t)bank * 4 + j) * BN; };

    logw_kernel<<<(BN + 255) / 256, 256>>>(alpha, beta, la_, lb_);

    cost_all<<<dim3(NPTS / 32, NPTS / 32, 24), dim3(32, 8)>>>(x, y, Cxx, Cyy, Cxy, Cyx);

    const double eps_list[8] = {
        4.0, 3.9999999999999996, 1.0, 0.25, 0.0625, 0.015625, 0.00390625, 0.0025
    };

    const unsigned short* CJ[4] = {Cxx, Cyy, Cyx, Cxy};
    const int GOUTI[4] = {0, 1, 3, 2};
    const float* LW[4] = {la_, lb_, lb_, la_};

    dim3 smg(BN / 4, 4);

    // ---- init (eps = 4), f16x2 exp ----
    {
        double eps = 4.0, eps_next = eps_list[0];
        SmJobs J;
        for (int j = 0; j < 4; j++) {
            J.C[j] = CJ[j];
            J.gin[j] = (j == 0 || j == 2) ? la_ : lb_;
            J.potold[j] = nullptr;
            J.out[j] = POT(0, j);
            J.gout[j] = G(0, GOUTI[j]);
            J.lw[j] = LW[j];
        }
        softmin_fused<true><<<smg, 256>>>(J, (float)(DQ * LOG2E / eps),
                                          (float)(-eps * LN2),
                                          (float)(LOG2E / eps_next), 0);
    }

    // ---- annealed loop, f16x2 exp (errors decay via 0.5-blend) ----
    int cur = 0, gb = 0;
    for (int i = 0; i < 8; i++) {
        double eps = eps_list[i];
        double eps_next = (i < 7) ? eps_list[i + 1] : 0.0025;
        int nxt = cur ^ 1;
        SmJobs J;
        for (int j = 0; j < 4; j++) {
            J.C[j] = CJ[j];
            J.gin[j] = G(gb, j);
            J.potold[j] = POT(cur, j);
            J.out[j] = POT(nxt, j);
            J.gout[j] = G(gb ^ 1, GOUTI[j]);
            J.lw[j] = LW[j];
        }
        softmin_fused<true><<<smg, 256>>>(J, (float)(DQ * LOG2E / eps),
                                          (float)(-eps * LN2),
                                          (float)(LOG2E / eps_next), 1);
        cur = nxt;
        gb ^= 1;
    }

    // ---- final extrapolation (eps = 0.0025), fp32 exp (undamped error path),
    //      SEQUENTIAL: b_x uses fresh a_y ----
    {
        double eps = 0.0025;
        float dqs = (float)(DQ * LOG2E / eps);
        float nel = (float)(-eps * LN2);
        float ien = (float)(LOG2E / eps);
        SmJobs J;
        for (int j = 0; j < 3; j++) {
            J.C[j] = CJ[j];
            J.gin[j] = G(gb, j);
            J.potold[j] = nullptr;
            J.out[j] = fin_ + (size_t)j * BN;
            J.gout[j] = (j == 2) ? G(gb ^ 1, 3) : nullptr;
            J.lw[j] = LW[j];
        }
        J.C[3] = CJ[3]; J.gin[3] = G(gb, 3); J.potold[3] = nullptr;
        J.out[3] = fin_ + 3 * (size_t)BN; J.gout[3] = nullptr; J.lw[3] = LW[3];
        softmin_fused<false><<<dim3(BN / 4, 3), 256>>>(J, dqs, nel, ien, 0);

        SmJobs J2;
        J2.C[0] = Cxy; J2.gin[0] = G(gb ^ 1, 3); J2.potold[0] = nullptr;
        J2.out[0] = fin_ + 3 * (size_t)BN; J2.gout[0] = nullptr; J2.lw[0] = lb_;
        softmin_fused<false><<<dim3(BN / 4, 1), 256>>>(J2, dqs, nel, ien, 0);
    }

    loss_kernel<<<B, 256>>>(alpha, beta, out);
}

// round 9
// speedup vs baseline: 3.0208x; 1.0801x over previous
#include <cuda_runtime.h>
#include <cuda_fp16.h>
#include <math.h>

#define B    8
#define NPTS 2048
#define BN   (B * NPTS)
#define CMAT ((size_t)B * NPTS * NPTS)

#define CMAX  1.5707964f
#define QSCL  (65535.0f / CMAX)
#define DQ    (1.5707964 / 65535.0)
#define LOG2E 1.4426950408889634
#define LN2   0.6931471805599453

// ---------------- scratch (allocation-free: __device__ globals) ----------------
__device__ unsigned short d_C[4][B * NPTS * NPTS];   // Cxx, Cyy, Cxy, Cyx
__device__ float d_pot[2][4][BN];
__device__ float d_fin[4][BN];
__device__ float d_g[2][4][BN];                      // double-buffered weights
__device__ float d_la[BN];                           // log2e * log(alpha)
__device__ float d_lb[BN];

// ---------------- helpers ----------------
__device__ __forceinline__ unsigned int qcost(float t) {
    t = fminf(fmaxf(t, -1.0f + 1e-6f), 1.0f - 1e-6f);
    float ax = fabsf(t);
    float s  = sqrtf(1.0f - ax);
    float p  = -0.0012624911f;
    p = fmaf(p, ax, 0.0066700901f);
    p = fmaf(p, ax, -0.0170881256f);
    p = fmaf(p, ax, 0.0308918810f);
    p = fmaf(p, ax, -0.0501743046f);
    p = fmaf(p, ax, 0.0889789874f);
    p = fmaf(p, ax, -0.2145988016f);
    p = fmaf(p, ax, 1.5707963050f);
    float r = s * p;
    float c = (t < 0.0f) ? (3.14159265359f - r) : r;
    return __float2uint_rn(c * 0.5f * QSCL);
}

// ---------------- kernels ----------------
__global__ void logw_kernel(const float* __restrict__ a, const float* __restrict__ bt,
                            float* __restrict__ la, float* __restrict__ lb) {
    int i = blockIdx.x * blockDim.x + threadIdx.x;
    if (i < BN) {
        float av = a[i];
        la[i] = (float)LOG2E * ((av > 0.f) ? logf(fmaxf(av, 1e-30f)) : -1e5f);
        float bv = bt[i];
        lb[i] = (float)LOG2E * ((bv > 0.f) ? logf(fmaxf(bv, 1e-30f)) : -1e5f);
    }
}

// All three cost jobs in one launch: z = job*8 + batch.
__global__ void cost_all(const float* __restrict__ x, const float* __restrict__ y,
                         unsigned short* __restrict__ Cxx, unsigned short* __restrict__ Cyy,
                         unsigned short* __restrict__ Cxy, unsigned short* __restrict__ Cyx) {
    int job = blockIdx.z >> 3;
    int b   = blockIdx.z & 7;
    const float *P, *Q;
    unsigned short *Co, *Ct;
    int tri;
    if (job == 0)      { P = x; Q = x; Co = Cxx; Ct = Cxx; tri = 1; }
    else if (job == 1) { P = y; Q = y; Co = Cyy; Ct = Cyy; tri = 1; }
    else               { P = x; Q = y; Co = Cxy; Ct = Cyx; tri = 0; }
    if (tri && (int)blockIdx.x < (int)blockIdx.y) return;

    __shared__ float xs[32][3], ys[32][3];
    __shared__ unsigned short t[32][33];
    int n0 = blockIdx.y * 32, m0 = blockIdx.x * 32;
    int tx = threadIdx.x, ty = threadIdx.y;
    int lt = ty * 32 + tx;
    if (lt < 96) {
        xs[lt / 3][lt % 3] = P[((size_t)b * NPTS + n0) * 3 + lt];
        ys[lt / 3][lt % 3] = Q[((size_t)b * NPTS + m0) * 3 + lt];
    }
    __syncthreads();
#pragma unroll
    for (int k = 0; k < 4; k++) {
        int nl = ty + 8 * k;
        float dot = xs[nl][0] * ys[tx][0] + xs[nl][1] * ys[tx][1] + xs[nl][2] * ys[tx][2];
        unsigned int q = qcost(dot);
        t[nl][tx] = (unsigned short)q;
        Co[((size_t)b * NPTS + n0 + nl) * NPTS + m0 + tx] = (unsigned short)q;
    }
    __syncthreads();
#pragma unroll
    for (int k = 0; k < 4; k++) {
        int ml = ty + 8 * k;
        Ct[((size_t)b * NPTS + m0 + ml) * NPTS + n0 + tx] = t[tx][ml];
    }
}

// ---- fused softmin v2: 512 threads = 16 warps = 8 rows x 2 halves per block.
// g staged in smem (split even/odd float4 for conflict-free LDS.128);
// per-warp local max, exact fp32 max-combine at finalize.
struct SmJobs {
    const unsigned short* C[4];
    const float*          gin[4];
    const float*          potold[4];
    float*                out[4];
    float*                gout[4];
    const float*          lw[4];
};

template <bool HEXP>
__global__ void __launch_bounds__(512) softmin_fused(
        SmJobs J, float dqs, float negeln2, float ienl2, int blend) {
    __shared__ float4 sgA[256];      // g elems 8i..8i+3
    __shared__ float4 sgB[256];      // g elems 8i+4..8i+7
    __shared__ float  sm_m[8][2];
    __shared__ float  sm_s[8][2];

    int tid  = threadIdx.x;
    int warp = tid >> 5, lane = tid & 31;
    int rloc = warp >> 1, half = warp & 1;
    int row  = blockIdx.x * 8 + rloc;
    int job  = blockIdx.y;
    int b    = row >> 11;

    // Stage g (2048 floats = 512 float4) into split smem arrays.
    {
        float4 gv = ((const float4*)(J.gin[job] + b * NPTS))[tid];
        if (tid & 1) sgB[tid >> 1] = gv; else sgA[tid >> 1] = gv;
    }

    // Front-batch the 4 C loads (independent of smem stage) before the barrier.
    const uint4* Cq = (const uint4*)(J.C[job] + (size_t)row * NPTS + half * 1024);
    uint4 q0 = __ldcs(Cq + lane);
    uint4 q1 = __ldcs(Cq + lane + 32);
    uint4 q2 = __ldcs(Cq + lane + 64);
    uint4 q3 = __ldcs(Cq + lane + 96);
    __syncthreads();

    // uint4 chunk k (index lane+32k) covers g elements [8*(128*half+lane+32k) .. +7],
    // i.e. split-array float4 index gb0 + 32*k.
    int gb0 = 128 * half + lane;
    float v[32];
    {
        float4 gA, gB;
        uint4 q;
#define V8(OFF, QQ)                                                       \
        q = QQ; gA = sgA[gb0 + (OFF) * 32]; gB = sgB[gb0 + (OFF) * 32];   \
        v[8*(OFF)+0] = fmaf((float)(q.x & 0xffff), -dqs, gA.x);           \
        v[8*(OFF)+1] = fmaf((float)(q.x >> 16),    -dqs, gA.y);           \
        v[8*(OFF)+2] = fmaf((float)(q.y & 0xffff), -dqs, gA.z);           \
        v[8*(OFF)+3] = fmaf((float)(q.y >> 16),    -dqs, gA.w);           \
        v[8*(OFF)+4] = fmaf((float)(q.z & 0xffff), -dqs, gB.x);           \
        v[8*(OFF)+5] = fmaf((float)(q.z >> 16),    -dqs, gB.y);           \
        v[8*(OFF)+6] = fmaf((float)(q.w & 0xffff), -dqs, gB.z);           \
        v[8*(OFF)+7] = fmaf((float)(q.w >> 16),    -dqs, gB.w)
        V8(0, q0); V8(1, q1); V8(2, q2); V8(3, q3);
#undef V8
    }

    // per-warp local max
    float m = v[0];
#pragma unroll
    for (int k = 1; k < 32; k++) m = fmaxf(m, v[k]);
#pragma unroll
    for (int o = 16; o; o >>= 1) m = fmaxf(m, __shfl_xor_sync(0xffffffffu, m, o));

    float s;
    if (HEXP) {
        __half2 a0 = __float2half2_rn(0.f), a1 = a0, a2 = a0, a3 = a0;
#pragma unroll
        for (int k = 0; k < 32; k += 8) {
            a0 = __hadd2(a0, h2exp2(__floats2half2_rn(v[k + 0] - m, v[k + 1] - m)));
            a1 = __hadd2(a1, h2exp2(__floats2half2_rn(v[k + 2] - m, v[k + 3] - m)));
            a2 = __hadd2(a2, h2exp2(__floats2half2_rn(v[k + 4] - m, v[k + 5] - m)));
            a3 = __hadd2(a3, h2exp2(__floats2half2_rn(v[k + 6] - m, v[k + 7] - m)));
        }
        float2 f0 = __half22float2(a0), f1 = __half22float2(a1);
        float2 f2 = __half22float2(a2), f3 = __half22float2(a3);
        s = ((f0.x + f0.y) + (f1.x + f1.y)) + ((f2.x + f2.y) + (f3.x + f3.y));
    } else {
        s = 0.f;
#pragma unroll
        for (int k = 0; k < 32; k++) s += exp2f(v[k] - m);
    }
#pragma unroll
    for (int o = 16; o; o >>= 1) s += __shfl_xor_sync(0xffffffffu, s, o);
    if (lane == 0) { sm_m[rloc][half] = m; sm_s[rloc][half] = s; }
    __syncthreads();

    if (tid < 8) {
        float m0 = sm_m[tid][0], m1 = sm_m[tid][1];
        float M  = fmaxf(m0, m1);
        float tot = sm_s[tid][0] * exp2f(m0 - M) + sm_s[tid][1] * exp2f(m1 - M);
        float r = negeln2 * (M + log2f(tot));
        int orow = blockIdx.x * 8 + tid;
        if (blend) r = 0.5f * (J.potold[job][orow] + r);
        J.out[job][orow] = r;
        if (J.gout[job])
            J.gout[job][orow] = fmaf(r, ienl2, J.lw[job][orow]);
    }
}

__global__ void loss_kernel(const float* __restrict__ alpha, const float* __restrict__ beta,
                            float* __restrict__ out) {
    __shared__ double red[8];
    int b = blockIdx.x, tid = threadIdx.x;
    double acc = 0.0;
    for (int i = tid; i < NPTS; i += 256) {
        int idx = b * NPTS + i;
        acc += (double)alpha[idx] * ((double)d_fin[3][idx] - (double)d_fin[0][idx]);
        acc += (double)beta[idx]  * ((double)d_fin[2][idx] - (double)d_fin[1][idx]);
    }
#pragma unroll
    for (int o = 16; o; o >>= 1)
        acc += __shfl_xor_sync(0xffffffffu, acc, o);
    if ((tid & 31) == 0) red[tid >> 5] = acc;
    __syncthreads();
    if (tid == 0) {
        double tot = red[0];
#pragma unroll
        for (int i = 1; i < 8; i++) tot += red[i];
        out[b] = (float)tot;
    }
}

// ---------------- host orchestration ----------------
extern "C" void kernel_launch(void* const* d_in, const int* in_sizes, int n_in,
                              void* d_out, int out_size) {
    const float* alpha = (const float*)d_in[0];
    const float* x     = (const float*)d_in[1];
    const float* beta  = (const float*)d_in[2];
    const float* y     = (const float*)d_in[3];
    float* out = (float*)d_out;

    unsigned short* C_;
    float *pot_, *fin_, *g_, *la_, *lb_;
    cudaGetSymbolAddress((void**)&C_,   d_C);
    cudaGetSymbolAddress((void**)&pot_, d_pot);
    cudaGetSymbolAddress((void**)&fin_, d_fin);
    cudaGetSymbolAddress((void**)&g_,   d_g);
    cudaGetSymbolAddress((void**)&la_,  d_la);
    cudaGetSymbolAddress((void**)&lb_,  d_lb);

    unsigned short* Cxx = C_ + 0 * CMAT;
    unsigned short* Cyy = C_ + 1 * CMAT;
    unsigned short* Cxy = C_ + 2 * CMAT;
    unsigned short* Cyx = C_ + 3 * CMAT;
    auto POT = [&](int buf, int j) { return pot_ + ((size_t)buf * 4 + j) * BN; };
    auto G   = [&](int bank, int j) { return g_ + ((size_t)bank * 4 + j) * BN; };

    logw_kernel<<<(BN + 255) / 256, 256>>>(alpha, beta, la_, lb_);

    cost_all<<<dim3(NPTS / 32, NPTS / 32, 24), dim3(32, 8)>>>(x, y, Cxx, Cyy, Cxy, Cyx);

    const double eps_list[8] = {
        4.0, 3.9999999999999996, 1.0, 0.25, 0.0625, 0.015625, 0.00390625, 0.0025
    };

    const unsigned short* CJ[4] = {Cxx, Cyy, Cyx, Cxy};
    const int GOUTI[4] = {0, 1, 3, 2};
    const float* LW[4] = {la_, lb_, lb_, la_};

    dim3 smg(BN / 8, 4);

    // ---- init (eps = 4) ----
    {
        double eps = 4.0, eps_next = eps_list[0];
        SmJobs J;
        for (int j = 0; j < 4; j++) {
            J.C[j] = CJ[j];
            J.gin[j] = (j == 0 || j == 2) ? la_ : lb_;
            J.potold[j] = nullptr;
            J.out[j] = POT(0, j);
            J.gout[j] = G(0, GOUTI[j]);
            J.lw[j] = LW[j];
        }
        softmin_fused<true><<<smg, 512>>>(J, (float)(DQ * LOG2E / eps),
                                          (float)(-eps * LN2),
                                          (float)(LOG2E / eps_next), 0);
    }

    // ---- annealed loop ----
    int cur = 0, gb = 0;
    for (int i = 0; i < 8; i++) {
        double eps = eps_list[i];
        double eps_next = (i < 7) ? eps_list[i + 1] : 0.0025;
        int nxt = cur ^ 1;
        SmJobs J;
        for (int j = 0; j < 4; j++) {
            J.C[j] = CJ[j];
            J.gin[j] = G(gb, j);
            J.potold[j] = POT(cur, j);
            J.out[j] = POT(nxt, j);
            J.gout[j] = G(gb ^ 1, GOUTI[j]);
            J.lw[j] = LW[j];
        }
        softmin_fused<true><<<smg, 512>>>(J, (float)(DQ * LOG2E / eps),
                                          (float)(-eps * LN2),
                                          (float)(LOG2E / eps_next), 1);
        cur = nxt;
        gb ^= 1;
    }

    // ---- final extrapolation (fp32 exp path), SEQUENTIAL: b_x uses fresh a_y ----
    {
        double eps = 0.0025;
        float dqs = (float)(DQ * LOG2E / eps);
        float nel = (float)(-eps * LN2);
        float ien = (float)(LOG2E / eps);
        SmJobs J;
        for (int j = 0; j < 3; j++) {
            J.C[j] = CJ[j];
            J.gin[j] = G(gb, j);
            J.potold[j] = nullptr;
            J.out[j] = fin_ + (size_t)j * BN;
            J.gout[j] = (j == 2) ? G(gb ^ 1, 3) : nullptr;
            J.lw[j] = LW[j];
        }
        J.C[3] = CJ[3]; J.gin[3] = G(gb, 3); J.potold[3] = nullptr;
        J.out[3] = fin_ + 3 * (size_t)BN; J.gout[3] = nullptr; J.lw[3] = LW[3];
        softmin_fused<false><<<dim3(BN / 8, 3), 512>>>(J, dqs, nel, ien, 0);

        SmJobs J2;
        J2.C[0] = Cxy; J2.gin[0] = G(gb ^ 1, 3); J2.potold[0] = nullptr;
        J2.out[0] = fin_ + 3 * (size_t)BN; J2.gout[0] = nullptr; J2.lw[0] = lb_;
        softmin_fused<false><<<dim3(BN / 8, 1), 512>>>(J2, dqs, nel, ien, 0);
    }

    loss_kernel<<<B, 256>>>(alpha, beta, out);
}